// round 4
// baseline (speedup 1.0000x reference)
#include <cuda_runtime.h>

#define Bsz 64
#define Ssz 512
#define Hsz 512
#define Isz 512

typedef unsigned long long u64;

// Scratch (allocation-free rule: __device__ globals)
__device__ float g_xw[134217728];        // [d][s][g][h][b] : 2*512*4*512*64 = 512MB
__device__ float g_h[2][2][Hsz][Bsz];    // [dir][buf][h][b]
__device__ float g_c[2][Hsz][Bsz];       // [dir][h][b]

__device__ __forceinline__ u64 packf2(float x, float y) {
    u64 r; asm("mov.b64 %0, {%1,%2};" : "=l"(r) : "f"(x), "f"(y)); return r;
}
__device__ __forceinline__ void unpack2(u64 v, float& x, float& y) {
    asm("mov.b64 {%0,%1}, %2;" : "=f"(x), "=f"(y) : "l"(v));
}
__device__ __forceinline__ void fma2(u64& d, u64 a, u64 b) {
    asm("fma.rn.f32x2 %0, %1, %2, %0;" : "+l"(d) : "l"(a), "l"(b));
}
__device__ __forceinline__ float sigm(float x) {
    float e; asm("ex2.approx.f32 %0, %1;" : "=f"(e) : "f"(x * -1.4426950408889634f));
    float r; asm("rcp.approx.f32 %0, %1;" : "=f"(r) : "f"(1.0f + e));
    return r;
}
__device__ __forceinline__ float tanh_(float x) {
    float e; asm("ex2.approx.f32 %0, %1;" : "=f"(e) : "f"(x * 2.8853900817779268f));
    float r; asm("rcp.approx.f32 %0, %1;" : "=f"(r) : "f"(1.0f + e));
    return 1.0f - 2.0f * r;
}

// ---------------------------------------------------------------------------
// Zero h/c state
__global__ void k_init() {
    int i = blockIdx.x * 256 + threadIdx.x;
    float* ph = &g_h[0][0][0][0];
    if (i < 2 * 2 * Hsz * Bsz) ph[i] = 0.0f;
    float* pc = &g_c[0][0][0];
    if (i < 2 * Hsz * Bsz) pc[i] = 0.0f;
}

// ---------------------------------------------------------------------------
// Input projection: xw[d][s][g][h][b] = sum_i x[b][s][i] * W_d[g][i][h] + b_d[g][h]
// Tile: 64 rows (all b of one s) x 64 cols (h within one gate). K = 512 in 16
// tiles of 32, single smem buffer with register prefetch.
// Threads 256: warp w owns cols 8w..8w+7 (as 4 col-pairs, f32x2-packed),
// lane l owns rows 2l, 2l+1.
__global__ __launch_bounds__(256) void k_xw(
    const float* __restrict__ x,
    const float* __restrict__ Wf, const float* __restrict__ Wb,
    const float* __restrict__ bf, const float* __restrict__ bb)
{
    __shared__ float As[32][66];   // As[k][row]
    __shared__ float Bs[32][68];   // Bs[k][col]

    const int tid = threadIdx.x;
    const int s = blockIdx.y;
    const int ct = blockIdx.x;             // 0..63
    const int d = ct >> 5;
    const int g = (ct >> 3) & 3;
    const int h0 = (ct & 7) * 64;

    const float* W = (d ? Wb : Wf) + (size_t)g * Hsz * Isz + h0;
    const float* bias = (d ? bb : bf) + g * Hsz + h0;

    const int ra = tid >> 3, k4 = tid & 7;     // A staging: rows ra, ra+32
    const int c4 = tid & 15, kb = tid >> 4;    // B staging: k rows kb, kb+16
    const float* xg = x + ((size_t)ra * Ssz + s) * Isz + k4 * 4;
    const size_t xrow2 = (size_t)32 * Ssz * Isz;

    const int l = tid & 31, w = tid >> 5;

    u64 acc[2][4] = {};   // acc[row 2l / 2l+1][col pair j] = {C[r][8w+2j], C[r][8w+2j+1]}

    float4 rA0 = *(const float4*)(xg);
    float4 rA1 = *(const float4*)(xg + xrow2);
    float4 rB0 = *(const float4*)(W + (size_t)kb * Hsz + c4 * 4);
    float4 rB1 = *(const float4*)(W + (size_t)(kb + 16) * Hsz + c4 * 4);

    for (int t = 0; t < 16; t++) {
        {
            int kk = k4 * 4;
            As[kk + 0][ra] = rA0.x; As[kk + 1][ra] = rA0.y;
            As[kk + 2][ra] = rA0.z; As[kk + 3][ra] = rA0.w;
            As[kk + 0][ra + 32] = rA1.x; As[kk + 1][ra + 32] = rA1.y;
            As[kk + 2][ra + 32] = rA1.z; As[kk + 3][ra + 32] = rA1.w;
            *(float4*)&Bs[kb][c4 * 4] = rB0;
            *(float4*)&Bs[kb + 16][c4 * 4] = rB1;
        }
        __syncthreads();
        if (t < 15) {
            int k0 = (t + 1) * 32;
            rA0 = *(const float4*)(xg + k0);
            rA1 = *(const float4*)(xg + xrow2 + k0);
            rB0 = *(const float4*)(W + (size_t)(k0 + kb) * Hsz + c4 * 4);
            rB1 = *(const float4*)(W + (size_t)(k0 + kb + 16) * Hsz + c4 * 4);
        }
        #pragma unroll
        for (int kk = 0; kk < 32; kk++) {
            float2 a = *(const float2*)&As[kk][2 * l];
            u64 a0 = packf2(a.x, a.x);
            u64 a1 = packf2(a.y, a.y);
            const u64* bp = (const u64*)&Bs[kk][8 * w];
            u64 b0 = bp[0], b1 = bp[1], b2 = bp[2], b3 = bp[3];
            fma2(acc[0][0], a0, b0); fma2(acc[0][1], a0, b1);
            fma2(acc[0][2], a0, b2); fma2(acc[0][3], a0, b3);
            fma2(acc[1][0], a1, b0); fma2(acc[1][1], a1, b1);
            fma2(acc[1][2], a1, b2); fma2(acc[1][3], a1, b3);
        }
        __syncthreads();
    }

    // Epilogue: add bias, write xw[d][s][g][h][b] (b innermost, coalesced pairs)
    size_t gb = (((size_t)d * Ssz + s) * 4 + g) * (size_t)Hsz * Bsz;
    #pragma unroll
    for (int j = 0; j < 4; j++) {
        float2 bb2 = *(const float2*)&bias[8 * w + 2 * j];
        float p0, p1, q0, q1;
        unpack2(acc[0][j], p0, p1);   // row 2l, cols (8w+2j, 8w+2j+1)
        unpack2(acc[1][j], q0, q1);   // row 2l+1
        int hc = h0 + 8 * w + 2 * j;
        *(float2*)&g_xw[gb + (size_t)hc * Bsz + 2 * l] =
            make_float2(p0 + bb2.x, q0 + bb2.x);
        *(float2*)&g_xw[gb + (size_t)(hc + 1) * Bsz + 2 * l] =
            make_float2(p1 + bb2.y, q1 + bb2.y);
    }
}

// ---------------------------------------------------------------------------
// One recurrence step, both directions. Grid 128: d = bx>>6, 8-h slab per block.
// Tile 64 rows (b) x 32 cols (4 gates x 8 h). Warp w owns h = hh0+w with all 4
// gates (cols pre-permuted to hh*4+g and pre-duplicated as {u,u} pairs in smem).
// Lane l owns row pair (2l, 2l+1), packed directly by LDS.64 from k-major A.
__global__ __launch_bounds__(256) void k_step(
    int t,
    const float* __restrict__ Uf, const float* __restrict__ Ub,
    float* __restrict__ out)
{
    __shared__ float As[32][68];   // As[k][b]
    __shared__ u64 Bs2[32][32];    // Bs2[k][hh*4+g] = {U, U}

    const int tid = threadIdx.x;
    const int d = blockIdx.x >> 6;
    const int hh0 = (blockIdx.x & 63) * 8;
    const int s = d ? (Ssz - 1 - t) : t;
    const int buf = t & 1;
    const float* U = d ? Ub : Uf;

    const int b4 = tid & 15, ka = tid >> 4;            // A staging
    const int gB = (tid & 31) >> 3, hhB = tid & 7;     // B staging
    const int kb = tid >> 5;
    const float* hprev = &g_h[d][buf][0][0];
    const float* Ucol = U + (size_t)gB * Hsz * Hsz + hh0 + hhB;

    const int l = tid & 31, w = tid >> 5;
    const int hcol = hh0 + w;

    // acc[g] = {gate_g[b=2l], gate_g[b=2l+1]}, seeded with xw (+bias)
    u64 acc[4];
    {
        size_t gb = ((size_t)d * Ssz + s) * 4 * (size_t)Hsz * Bsz;
        #pragma unroll
        for (int g = 0; g < 4; g++)
            acc[g] = *(const u64*)&g_xw[gb + ((size_t)g * Hsz + hcol) * Bsz + 2 * l];
    }

    float4 rA0 = *(const float4*)&hprev[(size_t)ka * Bsz + b4 * 4];
    float4 rA1 = *(const float4*)&hprev[(size_t)(ka + 16) * Bsz + b4 * 4];
    float rB[4];
    #pragma unroll
    for (int j = 0; j < 4; j++) rB[j] = Ucol[(size_t)(kb + 8 * j) * Hsz];

    for (int tt = 0; tt < 16; tt++) {
        *(float4*)&As[ka][b4 * 4] = rA0;
        *(float4*)&As[ka + 16][b4 * 4] = rA1;
        #pragma unroll
        for (int j = 0; j < 4; j++)
            Bs2[kb + 8 * j][hhB * 4 + gB] = packf2(rB[j], rB[j]);
        __syncthreads();
        if (tt < 15) {
            int k0 = (tt + 1) * 32;
            rA0 = *(const float4*)&hprev[(size_t)(k0 + ka) * Bsz + b4 * 4];
            rA1 = *(const float4*)&hprev[(size_t)(k0 + ka + 16) * Bsz + b4 * 4];
            #pragma unroll
            for (int j = 0; j < 4; j++)
                rB[j] = Ucol[(size_t)(k0 + kb + 8 * j) * Hsz];
        }
        #pragma unroll
        for (int kk = 0; kk < 32; kk++) {
            u64 a2 = *(const u64*)&As[kk][2 * l];   // {h_prev[2l][k], h_prev[2l+1][k]}
            const u64* bp = &Bs2[kk][4 * w];
            fma2(acc[0], a2, bp[0]);
            fma2(acc[1], a2, bp[1]);
            fma2(acc[2], a2, bp[2]);
            fma2(acc[3], a2, bp[3]);
        }
        __syncthreads();
    }

    // Pointwise LSTM cell (gate order: f, g, i, o)
    float f0, f1, gg0, gg1, i0, i1, o0, o1;
    unpack2(acc[0], f0, f1);
    unpack2(acc[1], gg0, gg1);
    unpack2(acc[2], i0, i1);
    unpack2(acc[3], o0, o1);

    float* cp = &g_c[d][hcol][2 * l];
    float2 cold = *(float2*)cp;
    float cn0 = cold.x * sigm(f0) + tanh_(gg0) * sigm(i0);
    float cn1 = cold.y * sigm(f1) + tanh_(gg1) * sigm(i1);
    *(float2*)cp = make_float2(cn0, cn1);

    float hv0 = sigm(o0) * tanh_(cn0);
    float hv1 = sigm(o1) * tanh_(cn1);
    *(float2*)&g_h[d][buf ^ 1][hcol][2 * l] = make_float2(hv0, hv1);

    // output[s][b][d*H + h]
    size_t ob = (size_t)s * (Bsz * 2 * Hsz) + (size_t)(2 * l) * (2 * Hsz)
              + (size_t)d * Hsz + hcol;
    out[ob] = hv0;
    out[ob + 2 * Hsz] = hv1;
}

// ---------------------------------------------------------------------------
// Final-state gather. Robust to mask stored as 1-byte bool OR int32.
__global__ void k_gather(const unsigned char* __restrict__ mask,
                         const float* __restrict__ out,
                         float* __restrict__ hf, float* __restrict__ hb)
{
    __shared__ int sred[256];
    __shared__ int smode;
    const int b = blockIdx.x, tid = threadIdx.x;

    if (tid == 0) {
        // Detect storage: int32 bools are 0/1 words; uint8 ones read as int32
        // give 0x01010101-style values.
        const int* ip = (const int*)mask;
        int bytemode = 0;
        for (int j = 0; j < 8; j++) {
            unsigned int v = (unsigned int)ip[j];
            if (v > 1u) bytemode = 1;
        }
        smode = bytemode;
    }
    __syncthreads();

    int v;
    if (smode) {
        v  = mask[b * Ssz + tid] ? 1 : 0;
        v += mask[b * Ssz + 256 + tid] ? 1 : 0;
    } else {
        const int* ip = (const int*)mask;
        v  = ip[b * Ssz + tid] ? 1 : 0;
        v += ip[b * Ssz + 256 + tid] ? 1 : 0;
    }
    sred[tid] = v;
    __syncthreads();
    for (int st = 128; st > 0; st >>= 1) {
        if (tid < st) sred[tid] += sred[tid + st];
        __syncthreads();
    }
    int len = sred[0];
    int idx = len > 0 ? len - 1 : 0;

    hf[b * Hsz + tid]       = out[(size_t)idx * 65536 + b * 1024 + tid];
    hf[b * Hsz + tid + 256] = out[(size_t)idx * 65536 + b * 1024 + tid + 256];
    hb[b * Hsz + tid]       = out[(size_t)b * 1024 + 512 + tid];
    hb[b * Hsz + tid + 256] = out[(size_t)b * 1024 + 512 + tid + 256];
}

// ---------------------------------------------------------------------------
extern "C" void kernel_launch(void* const* d_in, const int* in_sizes, int n_in,
                              void* d_out, int out_size)
{
    const float* x  = (const float*)d_in[0];
    const unsigned char* mask = (const unsigned char*)d_in[1];
    const float* Uf = (const float*)d_in[2];
    const float* Wf = (const float*)d_in[3];
    const float* bf = (const float*)d_in[4];
    const float* Ub = (const float*)d_in[5];
    const float* Wb = (const float*)d_in[6];
    const float* bb = (const float*)d_in[7];

    float* out = (float*)d_out;                       // [S][B][2H]
    float* hf  = out + (size_t)Ssz * Bsz * 2 * Hsz;   // [B][H]
    float* hb  = hf + (size_t)Bsz * Hsz;              // [B][H]

    k_init<<<512, 256>>>();

    dim3 gx(64, 512);
    k_xw<<<gx, 256>>>(x, Wf, Wb, bf, bb);

    for (int t = 0; t < Ssz; t++)
        k_step<<<128, 256>>>(t, Uf, Ub, out);

    k_gather<<<64, 256>>>(mask, out, hf, hb);
}